// round 14
// baseline (speedup 1.0000x reference)
#include <cuda_runtime.h>
#include <cuda_fp16.h>
#include <cstdint>

#define Bn 256
#define Tn 128
#define Hn 1024
#define Vn 32
#define Gn 4096
#define BH (Bn*Hn)
#define THB (Tn*BH)
#define NW (Gn*Hn)
#define MROWS (Tn*Bn)
#define LOGN (Bn*Tn*Vn)

__device__ __half g_Whh[3*NW];
__device__ __half g_Wih[2*NW];
__device__ float  g_Wih0T[Vn*Gn];
__device__ __half g_hs[2][THB];
__device__ float  g_xW[(size_t)MROWS*Gn];
__device__ __half g_hio[2][BH];
__device__ float  g_WoutT[Hn*Vn];
__device__ unsigned g_bar;

__device__ __forceinline__ void mma_f16(float* d, const uint32_t* a, const uint32_t* b) {
    asm volatile(
        "mma.sync.aligned.m16n8k16.row.col.f32.f16.f16.f32 "
        "{%0,%1,%2,%3},{%4,%5,%6,%7},{%8,%9},{%0,%1,%2,%3};\n"
        : "+f"(d[0]), "+f"(d[1]), "+f"(d[2]), "+f"(d[3])
        : "r"(a[0]), "r"(a[1]), "r"(a[2]), "r"(a[3]), "r"(b[0]), "r"(b[1]));
}
__device__ __forceinline__ void cpasync16(uint32_t daddr, const void* src) {
    asm volatile("cp.async.cg.shared.global [%0], [%1], 16;\n" :: "r"(daddr), "l"(src));
}
#define CP_COMMIT() asm volatile("cp.async.commit_group;\n")
#define CP_WAIT(n)  asm volatile("cp.async.wait_group %0;\n" :: "n"(n))

__device__ __forceinline__ float sigmoidf_(float x) {
    return __fdividef(1.0f, 1.0f + __expf(-x));
}
__device__ __forceinline__ float tanh_fast(float x) {
    float e = __expf(-2.0f * fabsf(x));
    return copysignf(__fdividef(1.0f - e, 1.0f + e), x);
}
__device__ __forceinline__ uint32_t smem_u32(const void* p) {
    uint32_t a;
    asm("{ .reg .u64 t; cvta.to.shared.u64 t, %1; cvt.u32.u64 %0, t; }" : "=r"(a) : "l"(p));
    return a;
}

// no-op: shifts launch index so ncu (-s 5) lands on rec_kernel
__global__ void dummy_kernel() {}

__global__ void prep_kernel(const float* __restrict__ Wih0, const float* __restrict__ Whh0,
                            const float* __restrict__ Wih_rest, const float* __restrict__ Whh_rest,
                            const float* __restrict__ Wout) {
    int i = blockIdx.x * blockDim.x + threadIdx.x;
    int stride = gridDim.x * blockDim.x;
    for (int idx = i; idx < NW; idx += stride) g_Whh[idx] = __float2half_rn(Whh0[idx]);
    for (int idx = i; idx < 2 * NW; idx += stride) {
        g_Whh[NW + idx] = __float2half_rn(Whh_rest[idx]);
        g_Wih[idx]      = __float2half_rn(Wih_rest[idx]);
    }
    for (int idx = i; idx < Gn * Vn; idx += stride) {
        int row = idx >> 5, v = idx & 31;
        g_Wih0T[(size_t)v * Gn + row] = Wih0[idx];
    }
    for (int idx = i; idx < Hn * Vn; idx += stride) {
        int v = idx >> 10, k = idx & 1023;
        g_WoutT[k * Vn + v] = Wout[idx];
    }
}

__global__ void zero_state() {
    int i = blockIdx.x * blockDim.x + threadIdx.x;
    if (i == 0) g_bar = 0;
    if (i < BH / 2) {
        reinterpret_cast<uint32_t*>(g_hio[0])[i] = 0u;
        reinterpret_cast<uint32_t*>(g_hio[1])[i] = 0u;
    }
}

// ---- gemmA: xW(fp32) = hs_prev(half) . Wih^T(half); 128x128 tiles ----
#define GAST_B 10240
#define GA_SMEM (4*GAST_B)
__global__ void __launch_bounds__(256) gemmA(int l) {
    extern __shared__ __align__(16) char gsraw[];
    const uint32_t gsu = smem_u32(gsraw);
    const __half* sAh = (const __half*)gsraw;
    const __half* sBh = (const __half*)(gsraw + 2 * GAST_B);

    const int tid = threadIdx.x, lane = tid & 31, wid = tid >> 5;
    const int wm = wid & 3, wn = wid >> 2;
    const int gid = lane >> 2, tig = lane & 3;
    const int nbase = blockIdx.x * 128, mb = blockIdx.y * 128;
    const __half* A  = g_hs[(l - 1) & 1] + (size_t)mb * Hn;
    const __half* Bw = g_Wih + (size_t)(l - 1) * NW + (size_t)nbase * Hn;

    float acc[2][8][4];
    #pragma unroll
    for (int a0 = 0; a0 < 2; a0++)
        #pragma unroll
        for (int a1 = 0; a1 < 8; a1++)
            #pragma unroll
            for (int a2 = 0; a2 < 4; a2++) acc[a0][a1][a2] = 0.f;

    #define GA_LOAD(kc) do {                                                   \
        uint32_t stA = gsu + ((kc) & 1) * GAST_B;                              \
        uint32_t stB = gsu + 2 * GAST_B + ((kc) & 1) * GAST_B;                 \
        _Pragma("unroll")                                                      \
        for (int it = 0; it < 2; it++) {                                       \
            int idx = tid + it * 256;                                          \
            int r = idx >> 2, seg = idx & 3;                                   \
            cpasync16(stA + r * 80 + seg * 16,                                 \
                      A + (size_t)r * Hn + (kc) * 32 + seg * 8);               \
            cpasync16(stB + r * 80 + seg * 16,                                 \
                      Bw + (size_t)r * Hn + (kc) * 32 + seg * 8);              \
        }                                                                      \
    } while (0)

    GA_LOAD(0); CP_COMMIT();
    for (int kc = 0; kc < 32; kc++) {
        if (kc + 1 < 32) GA_LOAD(kc + 1);
        CP_COMMIT(); CP_WAIT(1);
        __syncthreads();
        const __half* cA = sAh + (kc & 1) * (GAST_B / 2);
        const __half* cB = sBh + (kc & 1) * (GAST_B / 2);
        #pragma unroll
        for (int kk = 0; kk < 2; kk++) {
            const int kb = kk * 16;
            uint32_t a[2][4];
            #pragma unroll
            for (int mt = 0; mt < 2; mt++) {
                int r0 = wm * 32 + mt * 16 + gid;
                a[mt][0] = *(const uint32_t*)(cA + r0 * 40 + kb + 2 * tig);
                a[mt][1] = *(const uint32_t*)(cA + (r0 + 8) * 40 + kb + 2 * tig);
                a[mt][2] = *(const uint32_t*)(cA + r0 * 40 + kb + 2 * tig + 8);
                a[mt][3] = *(const uint32_t*)(cA + (r0 + 8) * 40 + kb + 2 * tig + 8);
            }
            uint32_t b[8][2];
            #pragma unroll
            for (int nt = 0; nt < 8; nt++) {
                int n0 = wn * 64 + nt * 8 + gid;
                b[nt][0] = *(const uint32_t*)(cB + n0 * 40 + kb + 2 * tig);
                b[nt][1] = *(const uint32_t*)(cB + n0 * 40 + kb + 2 * tig + 8);
            }
            #pragma unroll
            for (int mt = 0; mt < 2; mt++)
                #pragma unroll
                for (int nt = 0; nt < 8; nt++)
                    mma_f16(acc[mt][nt], a[mt], b[nt]);
        }
        __syncthreads();
    }
    #pragma unroll
    for (int mt = 0; mt < 2; mt++)
        #pragma unroll
        for (int nt = 0; nt < 8; nt++) {
            int r0 = mb + wm * 32 + mt * 16 + gid;
            int c0 = nbase + wn * 64 + nt * 8 + tig * 2;
            *reinterpret_cast<float2*>(g_xW + (size_t)r0 * Gn + c0) =
                make_float2(acc[mt][nt][0], acc[mt][nt][1]);
            *reinterpret_cast<float2*>(g_xW + (size_t)(r0 + 8) * Gn + c0) =
                make_float2(acc[mt][nt][2], acc[mt][nt][3]);
        }
}

// ---- Persistent recurrent kernel: 128 CTAs x 512 threads (16 warps) ----
// Warp w owns batch rows [w*16, w*16+16) (one m16 tile). 4-stage per-warp
// chunk pipeline (16 rows x 32 k-halves = 1280B/stage, depth 3).
// sW [32][1032] halves resident (66KB).
#define SWP 1032
#define SW_B (32*SWP*2)                    // 66048
#define AST_B 1280
#define NST 4
#define REC_SMEM (SW_B + 16*NST*AST_B)     // 66048 + 81920 = 147968

template<bool L0>
__global__ void __launch_bounds__(512, 1) rec_kernel(int layer,
        const float* __restrict__ bias, const int* __restrict__ tokens,
        const int* __restrict__ lengths, float* __restrict__ out) {
    extern __shared__ __align__(16) char smraw[];
    __shared__ float sBias[32];
    const uint32_t dynS = smem_u32(smraw);
    __half* sWh = (__half*)smraw;
    char*   sAc = smraw + SW_B;

    const int tid = threadIdx.x, lane = tid & 31, wid = tid >> 5;
    const int gid = lane >> 2, tig = lane & 3;
    const int jbase = blockIdx.x * 8;
    const int b    = tid & 255;            // batch row for pointwise
    const int hfc  = tid >> 8;             // 0/1: which 4-col half

    const __half* Whh = g_Whh + (size_t)layer * NW;
    #pragma unroll
    for (int it = 0; it < 8; it++) {
        int s = it * 512 + tid;            // 4096 16B segs
        int r = s >> 7, c16 = s & 127;
        int wr = ((r >> 3) << 10) + jbase + (r & 7);
        *reinterpret_cast<uint4*>((char*)sWh + r * (SWP * 2) + c16 * 16) =
            *reinterpret_cast<const uint4*>(Whh + (size_t)wr * Hn + c16 * 8);
    }
    if (tid < 32)
        sBias[tid] = bias[((tid >> 3) << 10) + jbase + (tid & 7)];

    float creg[4], hreg[4];
    #pragma unroll
    for (int j = 0; j < 4; j++) { creg[j] = 0.f; hreg[j] = 0.f; }
    const int lenb = lengths[b];
    const uint32_t aWu = dynS + SW_B + wid * (NST * AST_B);
    __syncthreads();

    // chunk = 32 k-halves of warp's 16 batch rows; 64 16B segs / 32 lanes
    #define REC_LOAD(kc) do {                                                  \
        uint32_t d0 = aWu + ((kc) & 3) * AST_B;                                \
        const __half* src_ = hwarp + (kc) * 32;                                \
        _Pragma("unroll")                                                      \
        for (int it = 0; it < 2; it++) {                                       \
            int idx = lane + it * 32;                                          \
            int r = idx >> 2, seg = idx & 3;                                   \
            cpasync16(d0 + r * 80 + seg * 16,                                  \
                      src_ + (size_t)r * Hn + seg * 8);                        \
        }                                                                      \
    } while (0)

    for (int t = 0; t < Tn; t++) {
        const __half* hwarp = g_hio[t & 1] + (size_t)(wid * 16) * Hn;
        const float* xbase = L0
            ? (g_Wih0T + (size_t)tokens[b * Tn + t] * Gn + jbase + hfc * 4)
            : (g_xW + (size_t)(t * Bn + b) * Gn + jbase + hfc * 4);
        float4 xv[4];
        #pragma unroll
        for (int g = 0; g < 4; g++)
            xv[g] = *reinterpret_cast<const float4*>(xbase + (g << 10));

        REC_LOAD(0); CP_COMMIT();
        REC_LOAD(1); CP_COMMIT();
        REC_LOAD(2); CP_COMMIT();

        float acc[4][4];
        #pragma unroll
        for (int a1 = 0; a1 < 4; a1++)
            #pragma unroll
            for (int a2 = 0; a2 < 4; a2++) acc[a1][a2] = 0.f;

        for (int kc = 0; kc < 32; kc++) {
            if (kc + 3 < 32) REC_LOAD(kc + 3);
            CP_COMMIT();
            CP_WAIT(3);
            __syncwarp();
            const __half* A = (const __half*)(sAc + wid * (NST * AST_B)
                                              + (kc & 3) * AST_B);
            const int kw0 = kc * 32;
            #pragma unroll
            for (int kk = 0; kk < 2; kk++) {
                const int kb = kk * 16;
                uint32_t a[4];
                a[0] = *(const uint32_t*)(A + gid * 40 + kb + 2 * tig);
                a[1] = *(const uint32_t*)(A + (gid + 8) * 40 + kb + 2 * tig);
                a[2] = *(const uint32_t*)(A + gid * 40 + kb + 2 * tig + 8);
                a[3] = *(const uint32_t*)(A + (gid + 8) * 40 + kb + 2 * tig + 8);
                uint32_t bf[4][2];
                #pragma unroll
                for (int nt = 0; nt < 4; nt++) {
                    int n0 = nt * 8 + gid;
                    bf[nt][0] = *(const uint32_t*)(sWh + n0 * SWP + kw0 + kb + 2 * tig);
                    bf[nt][1] = *(const uint32_t*)(sWh + n0 * SWP + kw0 + kb + 2 * tig + 8);
                }
                #pragma unroll
                for (int nt = 0; nt < 4; nt++)
                    mma_f16(acc[nt], a, bf[nt]);
            }
            __syncwarp();
        }

        __syncthreads();
        float* gsm = (float*)sAc;          // [32 gate][257] over batch (32896B)
        #pragma unroll
        for (int nt = 0; nt < 4; nt++) {
            int r0 = wid * 16 + gid;
            int c0 = nt * 8 + tig * 2;
            gsm[c0 * 257 + r0]           = acc[nt][0];
            gsm[(c0 + 1) * 257 + r0]     = acc[nt][1];
            gsm[c0 * 257 + r0 + 8]       = acc[nt][2];
            gsm[(c0 + 1) * 257 + r0 + 8] = acc[nt][3];
        }
        __syncthreads();

        __half h4[4];
        const bool msk = (t < lenb);
        const float xf[4][4] = {
            {xv[0].x, xv[0].y, xv[0].z, xv[0].w},
            {xv[1].x, xv[1].y, xv[1].z, xv[1].w},
            {xv[2].x, xv[2].y, xv[2].z, xv[2].w},
            {xv[3].x, xv[3].y, xv[3].z, xv[3].w}};
        #pragma unroll
        for (int q = 0; q < 4; q++) {
            int jl = hfc * 4 + q;
            float gi = gsm[(jl)      * 257 + b] + sBias[jl]      + xf[0][q];
            float gf = gsm[(8 + jl)  * 257 + b] + sBias[8 + jl]  + xf[1][q];
            float gg = gsm[(16 + jl) * 257 + b] + sBias[16 + jl] + xf[2][q];
            float go = gsm[(24 + jl) * 257 + b] + sBias[24 + jl] + xf[3][q];
            float i = sigmoidf_(gi);
            float f = sigmoidf_(gf);
            float g = tanh_fast(gg);
            float o = sigmoidf_(go);
            float cn = f * creg[q] + i * g;
            float hn = o * tanh_fast(cn);
            float hv = msk ? hn : hreg[q];
            float cv = msk ? cn : creg[q];
            creg[q] = cv; hreg[q] = hv;
            h4[q] = __float2half_rn(hv);
        }
        __half* hioOut = g_hio[(t + 1) & 1] + (size_t)b * Hn + jbase + hfc * 4;
        __half* hsOut  = g_hs[layer & 1] + (size_t)t * BH + (size_t)b * Hn + jbase + hfc * 4;
        *reinterpret_cast<uint2*>(hioOut) = *reinterpret_cast<uint2*>(h4);
        *reinterpret_cast<uint2*>(hsOut)  = *reinterpret_cast<uint2*>(h4);

        __threadfence();
        __syncthreads();
        if (tid == 0) {
            atomicAdd(&g_bar, 1u);
            unsigned tgt = 128u * (unsigned)(t + 1);
            unsigned v;
            do {
                asm volatile("ld.acquire.gpu.u32 %0, [%1];" : "=r"(v) : "l"(&g_bar));
                if (v < tgt) __nanosleep(32);
            } while (v < tgt);
        }
        __syncthreads();
    }

    float* oh = out + LOGN + (size_t)layer * BH + (size_t)b * Hn + jbase + hfc * 4;
    float* oc = out + LOGN + (size_t)3 * BH + (size_t)layer * BH + (size_t)b * Hn + jbase + hfc * 4;
    *reinterpret_cast<float4*>(oh) = make_float4(hreg[0], hreg[1], hreg[2], hreg[3]);
    *reinterpret_cast<float4*>(oc) = make_float4(creg[0], creg[1], creg[2], creg[3]);
}

__global__ void __launch_bounds__(256) logits_kernel(const float* __restrict__ bout,
                                                     const int* __restrict__ lengths,
                                                     float* __restrict__ out) {
    int gw = (blockIdx.x * blockDim.x + threadIdx.x) >> 5;
    int lane = threadIdx.x & 31;
    const __half* hs = g_hs[0];
    int row0 = gw * 4;
    const __half* hp = hs + (size_t)row0 * Hn;
    float acc0 = 0.f, acc1 = 0.f, acc2 = 0.f, acc3 = 0.f;
    for (int k0 = 0; k0 < Hn; k0 += 32) {
        float h0 = __half2float(hp[k0 + lane]);
        float h1 = __half2float(hp[Hn + k0 + lane]);
        float h2 = __half2float(hp[2 * Hn + k0 + lane]);
        float h3 = __half2float(hp[3 * Hn + k0 + lane]);
        #pragma unroll
        for (int i = 0; i < 32; i++) {
            float w = g_WoutT[(k0 + i) * Vn + lane];
            acc0 += __shfl_sync(0xffffffffu, h0, i) * w;
            acc1 += __shfl_sync(0xffffffffu, h1, i) * w;
            acc2 += __shfl_sync(0xffffffffu, h2, i) * w;
            acc3 += __shfl_sync(0xffffffffu, h3, i) * w;
        }
    }
    float bo = bout[lane];
    float accs[4] = {acc0, acc1, acc2, acc3};
    #pragma unroll
    for (int r = 0; r < 4; r++) {
        int row = row0 + r;
        int t = row >> 8, bb = row & 255;
        float v = (t < lengths[bb]) ? (accs[r] + bo) : 0.f;
        out[((size_t)bb * Tn + t) * Vn + lane] = v;
    }
}

extern "C" void kernel_launch(void* const* d_in, const int* in_sizes, int n_in,
                              void* d_out, int out_size) {
    const int*   tokens  = (const int*)d_in[0];
    const int*   lengths = (const int*)d_in[1];
    const float* Wih0    = (const float*)d_in[2];
    const float* Whh0    = (const float*)d_in[3];
    const float* b0      = (const float*)d_in[4];
    const float* Wih_r   = (const float*)d_in[5];
    const float* Whh_r   = (const float*)d_in[6];
    const float* b_r     = (const float*)d_in[7];
    const float* Wout    = (const float*)d_in[8];
    const float* bout    = (const float*)d_in[9];
    float* out = (float*)d_out;

    static bool attrDone = false;
    if (!attrDone) {
        cudaFuncSetAttribute(rec_kernel<true>,
                             cudaFuncAttributeMaxDynamicSharedMemorySize, REC_SMEM);
        cudaFuncSetAttribute(rec_kernel<false>,
                             cudaFuncAttributeMaxDynamicSharedMemorySize, REC_SMEM);
        cudaFuncSetAttribute(gemmA,
                             cudaFuncAttributeMaxDynamicSharedMemorySize, GA_SMEM);
        attrDone = true;
    }

    dummy_kernel<<<1, 32>>>();   // shifts ncu -s 5 capture onto rec_kernel<true>

    prep_kernel<<<1024, 256>>>(Wih0, Whh0, Wih_r, Whh_r, Wout);

    for (int l = 0; l < 3; l++) {
        zero_state<<<1024, 256>>>();
        if (l > 0) gemmA<<<dim3(32, 256), 256, GA_SMEM>>>(l);
        const float* bias = (l == 0) ? b0 : (b_r + (size_t)(l - 1) * Gn);
        if (l == 0)
            rec_kernel<true><<<128, 512, REC_SMEM>>>(l, bias, tokens, lengths, out);
        else
            rec_kernel<false><<<128, 512, REC_SMEM>>>(l, bias, tokens, lengths, out);
    }
    logits_kernel<<<1024, 256>>>(bout, lengths, out);
}

// round 16
// speedup vs baseline: 1.0959x; 1.0959x over previous
#include <cuda_runtime.h>
#include <cuda_fp16.h>
#include <cstdint>

#define Bn 256
#define Tn 128
#define Hn 1024
#define Vn 32
#define Gn 4096
#define BH (Bn*Hn)
#define THB (Tn*BH)
#define NW (Gn*Hn)
#define MROWS (Tn*Bn)
#define LOGN (Bn*Tn*Vn)

__device__ __half g_Whh[3*NW];
__device__ __half g_Wih[2*NW];
__device__ float  g_Wih0T[Vn*Gn];
__device__ __half g_hs[2][THB];
__device__ float  g_xW[(size_t)MROWS*Gn];
__device__ __half g_hio[2][BH];
__device__ float  g_WoutT[Hn*Vn];
__device__ unsigned g_bar;

__device__ __forceinline__ void mma_f16(float* d, const uint32_t* a, const uint32_t* b) {
    asm volatile(
        "mma.sync.aligned.m16n8k16.row.col.f32.f16.f16.f32 "
        "{%0,%1,%2,%3},{%4,%5,%6,%7},{%8,%9},{%0,%1,%2,%3};\n"
        : "+f"(d[0]), "+f"(d[1]), "+f"(d[2]), "+f"(d[3])
        : "r"(a[0]), "r"(a[1]), "r"(a[2]), "r"(a[3]), "r"(b[0]), "r"(b[1]));
}
__device__ __forceinline__ void ldsm4(uint32_t* r, uint32_t addr) {
    asm volatile("ldmatrix.sync.aligned.m8n8.x4.shared.b16 {%0,%1,%2,%3}, [%4];"
        : "=r"(r[0]), "=r"(r[1]), "=r"(r[2]), "=r"(r[3]) : "r"(addr));
}
__device__ __forceinline__ void cpasync16(uint32_t daddr, const void* src) {
    asm volatile("cp.async.cg.shared.global [%0], [%1], 16;\n" :: "r"(daddr), "l"(src));
}
#define CP_COMMIT() asm volatile("cp.async.commit_group;\n")
#define CP_WAIT(n)  asm volatile("cp.async.wait_group %0;\n" :: "n"(n))

__device__ __forceinline__ float sigmoidf_(float x) {
    return __fdividef(1.0f, 1.0f + __expf(-x));
}
__device__ __forceinline__ float tanh_fast(float x) {
    float e = __expf(-2.0f * fabsf(x));
    return copysignf(__fdividef(1.0f - e, 1.0f + e), x);
}
__device__ __forceinline__ uint32_t smem_u32(const void* p) {
    uint32_t a;
    asm("{ .reg .u64 t; cvta.to.shared.u64 t, %1; cvt.u32.u64 %0, t; }" : "=r"(a) : "l"(p));
    return a;
}

// no-op: shifts launch index so ncu (-s 5) lands on rec_kernel
__global__ void dummy_kernel() {}

__global__ void prep_kernel(const float* __restrict__ Wih0, const float* __restrict__ Whh0,
                            const float* __restrict__ Wih_rest, const float* __restrict__ Whh_rest,
                            const float* __restrict__ Wout) {
    int i = blockIdx.x * blockDim.x + threadIdx.x;
    int stride = gridDim.x * blockDim.x;
    for (int idx = i; idx < NW; idx += stride) g_Whh[idx] = __float2half_rn(Whh0[idx]);
    for (int idx = i; idx < 2 * NW; idx += stride) {
        g_Whh[NW + idx] = __float2half_rn(Whh_rest[idx]);
        g_Wih[idx]      = __float2half_rn(Wih_rest[idx]);
    }
    for (int idx = i; idx < Gn * Vn; idx += stride) {
        int row = idx >> 5, v = idx & 31;
        g_Wih0T[(size_t)v * Gn + row] = Wih0[idx];
    }
    for (int idx = i; idx < Hn * Vn; idx += stride) {
        int v = idx >> 10, k = idx & 1023;
        g_WoutT[k * Vn + v] = Wout[idx];
    }
}

__global__ void zero_state() {
    int i = blockIdx.x * blockDim.x + threadIdx.x;
    if (i == 0) g_bar = 0;
    if (i < BH / 2) {
        reinterpret_cast<uint32_t*>(g_hio[0])[i] = 0u;
        reinterpret_cast<uint32_t*>(g_hio[1])[i] = 0u;
    }
}

// ---- gemmA: xW(fp32) = hs_prev(half) . Wih^T(half); 128x128 tiles ----
#define GAST_B 10240
#define GA_SMEM (4*GAST_B)
__global__ void __launch_bounds__(256) gemmA(int l) {
    extern __shared__ __align__(16) char gsraw[];
    const uint32_t gsu = smem_u32(gsraw);
    const __half* sAh = (const __half*)gsraw;
    const __half* sBh = (const __half*)(gsraw + 2 * GAST_B);

    const int tid = threadIdx.x, lane = tid & 31, wid = tid >> 5;
    const int wm = wid & 3, wn = wid >> 2;
    const int gid = lane >> 2, tig = lane & 3;
    const int nbase = blockIdx.x * 128, mb = blockIdx.y * 128;
    const __half* A  = g_hs[(l - 1) & 1] + (size_t)mb * Hn;
    const __half* Bw = g_Wih + (size_t)(l - 1) * NW + (size_t)nbase * Hn;

    float acc[2][8][4];
    #pragma unroll
    for (int a0 = 0; a0 < 2; a0++)
        #pragma unroll
        for (int a1 = 0; a1 < 8; a1++)
            #pragma unroll
            for (int a2 = 0; a2 < 4; a2++) acc[a0][a1][a2] = 0.f;

    #define GA_LOAD(kc) do {                                                   \
        uint32_t stA = gsu + ((kc) & 1) * GAST_B;                              \
        uint32_t stB = gsu + 2 * GAST_B + ((kc) & 1) * GAST_B;                 \
        _Pragma("unroll")                                                      \
        for (int it = 0; it < 2; it++) {                                       \
            int idx = tid + it * 256;                                          \
            int r = idx >> 2, seg = idx & 3;                                   \
            cpasync16(stA + r * 80 + seg * 16,                                 \
                      A + (size_t)r * Hn + (kc) * 32 + seg * 8);               \
            cpasync16(stB + r * 80 + seg * 16,                                 \
                      Bw + (size_t)r * Hn + (kc) * 32 + seg * 8);              \
        }                                                                      \
    } while (0)

    GA_LOAD(0); CP_COMMIT();
    for (int kc = 0; kc < 32; kc++) {
        if (kc + 1 < 32) GA_LOAD(kc + 1);
        CP_COMMIT(); CP_WAIT(1);
        __syncthreads();
        const __half* cA = sAh + (kc & 1) * (GAST_B / 2);
        const __half* cB = sBh + (kc & 1) * (GAST_B / 2);
        #pragma unroll
        for (int kk = 0; kk < 2; kk++) {
            const int kb = kk * 16;
            uint32_t a[2][4];
            #pragma unroll
            for (int mt = 0; mt < 2; mt++) {
                int r0 = wm * 32 + mt * 16 + gid;
                a[mt][0] = *(const uint32_t*)(cA + r0 * 40 + kb + 2 * tig);
                a[mt][1] = *(const uint32_t*)(cA + (r0 + 8) * 40 + kb + 2 * tig);
                a[mt][2] = *(const uint32_t*)(cA + r0 * 40 + kb + 2 * tig + 8);
                a[mt][3] = *(const uint32_t*)(cA + (r0 + 8) * 40 + kb + 2 * tig + 8);
            }
            uint32_t b[8][2];
            #pragma unroll
            for (int nt = 0; nt < 8; nt++) {
                int n0 = wn * 64 + nt * 8 + gid;
                b[nt][0] = *(const uint32_t*)(cB + n0 * 40 + kb + 2 * tig);
                b[nt][1] = *(const uint32_t*)(cB + n0 * 40 + kb + 2 * tig + 8);
            }
            #pragma unroll
            for (int mt = 0; mt < 2; mt++)
                #pragma unroll
                for (int nt = 0; nt < 8; nt++)
                    mma_f16(acc[mt][nt], a[mt], b[nt]);
        }
        __syncthreads();
    }
    #pragma unroll
    for (int mt = 0; mt < 2; mt++)
        #pragma unroll
        for (int nt = 0; nt < 8; nt++) {
            int r0 = mb + wm * 32 + mt * 16 + gid;
            int c0 = nbase + wn * 64 + nt * 8 + tig * 2;
            *reinterpret_cast<float2*>(g_xW + (size_t)r0 * Gn + c0) =
                make_float2(acc[mt][nt][0], acc[mt][nt][1]);
            *reinterpret_cast<float2*>(g_xW + (size_t)(r0 + 8) * Gn + c0) =
                make_float2(acc[mt][nt][2], acc[mt][nt][3]);
        }
}

// ---- Persistent recurrent kernel (fp16), 128 CTAs x 8 cols, ldmatrix ----
// sW [32][1032] halves resident (66KB). Per-warp 4-stage chunk pipeline
// (32 rows x 32 k-halves = 2560B/stage, prefetch depth 3). Fragment loads
// via ldmatrix.x4: 8 ops/chunk (4 A + 4 B) feeding 8 MMAs.
#define SWP 1032
#define SW_B (32*SWP*2)                    // 66048
#define AST_B 2560
#define NST 4
#define REC_SMEM (SW_B + 8*NST*AST_B)      // 147968

template<bool L0>
__global__ void __launch_bounds__(256, 1) rec_kernel(int layer,
        const float* __restrict__ bias, const int* __restrict__ tokens,
        const int* __restrict__ lengths, float* __restrict__ out) {
    extern __shared__ __align__(16) char smraw[];
    __shared__ float sBias[32];
    const uint32_t dynS = smem_u32(smraw);
    __half* sWh = (__half*)smraw;
    char*   sAc = smraw + SW_B;

    const int tid = threadIdx.x, lane = tid & 31, wid = tid >> 5;
    const int jbase = blockIdx.x * 8;
    const int b = tid;
    const int lm = lane >> 3, l7 = lane & 7;   // ldmatrix lane decomposition

    // ldmatrix per-lane base offsets (bytes)
    // A tile rows pitch 80B: mats {r,k},{r+8,k},{r,k+8},{r+8,k+8}
    const uint32_t laneA = (uint32_t)(((lm & 1) * 8 + l7) * 80 + (lm >> 1) * 16);
    // B rows pitch SWP*2: mats {n,kb},{n,kb+8},{n+8,kb},{n+8,kb+8}
    const uint32_t laneB = (uint32_t)(((lm >> 1) * 8 + l7) * (SWP * 2) + (lm & 1) * 16);

    const __half* Whh = g_Whh + (size_t)layer * NW;
    #pragma unroll
    for (int it = 0; it < 16; it++) {
        int s = it * 256 + tid;            // 4096 16B segs
        int r = s >> 7, c16 = s & 127;
        int wr = ((r >> 3) << 10) + jbase + (r & 7);
        *reinterpret_cast<uint4*>((char*)sWh + r * (SWP * 2) + c16 * 16) =
            *reinterpret_cast<const uint4*>(Whh + (size_t)wr * Hn + c16 * 8);
    }
    if (tid < 32)
        sBias[tid] = bias[((tid >> 3) << 10) + jbase + (tid & 7)];

    float creg[8], hreg[8];
    #pragma unroll
    for (int j = 0; j < 8; j++) { creg[j] = 0.f; hreg[j] = 0.f; }
    const int lenb = lengths[b];
    const uint32_t aWu = dynS + SW_B + wid * (NST * AST_B);
    __syncthreads();

    #define REC_LOAD(kc) do {                                                  \
        uint32_t d0 = aWu + ((kc) & 3) * AST_B;                                \
        const __half* src_ = hwarp + (kc) * 32;                                \
        _Pragma("unroll")                                                      \
        for (int it = 0; it < 4; it++) {                                       \
            int idx = lane + it * 32;                                          \
            int r = idx >> 2, seg = idx & 3;                                   \
            cpasync16(d0 + r * 80 + seg * 16,                                  \
                      src_ + (size_t)r * Hn + seg * 8);                        \
        }                                                                      \
    } while (0)

    for (int t = 0; t < Tn; t++) {
        const __half* hwarp = g_hio[t & 1] + (size_t)(wid * 32) * Hn;
        const float* xbase = L0
            ? (g_Wih0T + (size_t)tokens[b * Tn + t] * Gn + jbase)
            : (g_xW + (size_t)(t * Bn + b) * Gn + jbase);
        float4 xv[4][2];
        #pragma unroll
        for (int g = 0; g < 4; g++) {
            xv[g][0] = *reinterpret_cast<const float4*>(xbase + (g << 10));
            xv[g][1] = *reinterpret_cast<const float4*>(xbase + (g << 10) + 4);
        }

        REC_LOAD(0); CP_COMMIT();
        REC_LOAD(1); CP_COMMIT();
        REC_LOAD(2); CP_COMMIT();

        float acc[2][4][4];
        #pragma unroll
        for (int a0 = 0; a0 < 2; a0++)
            #pragma unroll
            for (int a1 = 0; a1 < 4; a1++)
                #pragma unroll
                for (int a2 = 0; a2 < 4; a2++) acc[a0][a1][a2] = 0.f;

        for (int kc = 0; kc < 32; kc++) {
            if (kc + 3 < 32) REC_LOAD(kc + 3);
            CP_COMMIT();
            CP_WAIT(3);
            __syncwarp();
            const uint32_t stg = aWu + (kc & 3) * AST_B + laneA;
            const uint32_t bb  = dynS + laneB + (uint32_t)kc * 64;

            uint32_t a[2][2][4];           // [mt][kk][4]
            #pragma unroll
            for (int mt = 0; mt < 2; mt++)
                #pragma unroll
                for (int kk = 0; kk < 2; kk++)
                    ldsm4(a[mt][kk], stg + mt * 1280 + kk * 32);
            uint32_t bv[2][2][4];          // [kk][ntp]: {b[n0][0],b[n0][1],b[n1][0],b[n1][1]}
            #pragma unroll
            for (int kk = 0; kk < 2; kk++)
                #pragma unroll
                for (int ntp = 0; ntp < 2; ntp++)
                    ldsm4(bv[kk][ntp], bb + ntp * (16 * SWP * 2) + kk * 32);

            #pragma unroll
            for (int kk = 0; kk < 2; kk++)
                #pragma unroll
                for (int mt = 0; mt < 2; mt++)
                    #pragma unroll
                    for (int ntp = 0; ntp < 2; ntp++) {
                        mma_f16(acc[mt][ntp * 2],     a[mt][kk], &bv[kk][ntp][0]);
                        mma_f16(acc[mt][ntp * 2 + 1], a[mt][kk], &bv[kk][ntp][2]);
                    }
            __syncwarp();
        }

        __syncthreads();
        float* gsm = (float*)sAc;          // [32 gate][257] over batch (32896B)
        const int gid = lane >> 2, tig = lane & 3;
        #pragma unroll
        for (int mt = 0; mt < 2; mt++)
            #pragma unroll
            for (int nt = 0; nt < 4; nt++) {
                int r0 = wid * 32 + mt * 16 + gid;
                int c0 = nt * 8 + tig * 2;
                gsm[c0 * 257 + r0]           = acc[mt][nt][0];
                gsm[(c0 + 1) * 257 + r0]     = acc[mt][nt][1];
                gsm[c0 * 257 + r0 + 8]       = acc[mt][nt][2];
                gsm[(c0 + 1) * 257 + r0 + 8] = acc[mt][nt][3];
            }
        __syncthreads();

        float xf[4][8];
        #pragma unroll
        for (int g = 0; g < 4; g++) {
            xf[g][0] = xv[g][0].x; xf[g][1] = xv[g][0].y;
            xf[g][2] = xv[g][0].z; xf[g][3] = xv[g][0].w;
            xf[g][4] = xv[g][1].x; xf[g][5] = xv[g][1].y;
            xf[g][6] = xv[g][1].z; xf[g][7] = xv[g][1].w;
        }
        __half h8[8];
        const bool msk = (t < lenb);
        #pragma unroll
        for (int jl = 0; jl < 8; jl++) {
            float gi = gsm[(jl)      * 257 + b] + sBias[jl]      + xf[0][jl];
            float gf = gsm[(8 + jl)  * 257 + b] + sBias[8 + jl]  + xf[1][jl];
            float gg = gsm[(16 + jl) * 257 + b] + sBias[16 + jl] + xf[2][jl];
            float go = gsm[(24 + jl) * 257 + b] + sBias[24 + jl] + xf[3][jl];
            float i = sigmoidf_(gi);
            float f = sigmoidf_(gf);
            float g = tanh_fast(gg);
            float o = sigmoidf_(go);
            float cn = f * creg[jl] + i * g;
            float hn = o * tanh_fast(cn);
            float hv = msk ? hn : hreg[jl];
            float cv = msk ? cn : creg[jl];
            creg[jl] = cv; hreg[jl] = hv;
            h8[jl] = __float2half_rn(hv);
        }
        __half* hioOut = g_hio[(t + 1) & 1] + (size_t)b * Hn + jbase;
        __half* hsOut  = g_hs[layer & 1] + (size_t)t * BH + (size_t)b * Hn + jbase;
        *reinterpret_cast<uint4*>(hioOut) = *reinterpret_cast<uint4*>(h8);
        *reinterpret_cast<uint4*>(hsOut)  = *reinterpret_cast<uint4*>(h8);

        __threadfence();
        __syncthreads();
        if (tid == 0) {
            atomicAdd(&g_bar, 1u);
            unsigned tgt = 128u * (unsigned)(t + 1);
            unsigned v;
            do {
                asm volatile("ld.acquire.gpu.u32 %0, [%1];" : "=r"(v) : "l"(&g_bar));
                if (v < tgt) __nanosleep(32);
            } while (v < tgt);
        }
        __syncthreads();
    }

    float* oh = out + LOGN + (size_t)layer * BH + (size_t)b * Hn + jbase;
    float* oc = out + LOGN + (size_t)3 * BH + (size_t)layer * BH + (size_t)b * Hn + jbase;
    *reinterpret_cast<float4*>(oh)     = make_float4(hreg[0], hreg[1], hreg[2], hreg[3]);
    *reinterpret_cast<float4*>(oh + 4) = make_float4(hreg[4], hreg[5], hreg[6], hreg[7]);
    *reinterpret_cast<float4*>(oc)     = make_float4(creg[0], creg[1], creg[2], creg[3]);
    *reinterpret_cast<float4*>(oc + 4) = make_float4(creg[4], creg[5], creg[6], creg[7]);
}

__global__ void __launch_bounds__(256) logits_kernel(const float* __restrict__ bout,
                                                     const int* __restrict__ lengths,
                                                     float* __restrict__ out) {
    int gw = (blockIdx.x * blockDim.x + threadIdx.x) >> 5;
    int lane = threadIdx.x & 31;
    const __half* hs = g_hs[0];
    int row0 = gw * 4;
    const __half* hp = hs + (size_t)row0 * Hn;
    float acc0 = 0.f, acc1 = 0.f, acc2 = 0.f, acc3 = 0.f;
    for (int k0 = 0; k0 < Hn; k0 += 32) {
        float h0 = __half2float(hp[k0 + lane]);
        float h1 = __half2float(hp[Hn + k0 + lane]);
        float h2 = __half2float(hp[2 * Hn + k0 + lane]);
        float h3 = __half2float(hp[3 * Hn + k0 + lane]);
        #pragma unroll
        for (int i = 0; i < 32; i++) {
            float w = g_WoutT[(k0 + i) * Vn + lane];
            acc0 += __shfl_sync(0xffffffffu, h0, i) * w;
            acc1 += __shfl_sync(0xffffffffu, h1, i) * w;
            acc2 += __shfl_sync(0xffffffffu, h2, i) * w;
            acc3 += __shfl_sync(0xffffffffu, h3, i) * w;
        }
    }
    float bo = bout[lane];
    float accs[4] = {acc0, acc1, acc2, acc3};
    #pragma unroll
    for (int r = 0; r < 4; r++) {
        int row = row0 + r;
        int t = row >> 8, bb = row & 255;
        float v = (t < lengths[bb]) ? (accs[r] + bo) : 0.f;
        out[((size_t)bb * Tn + t) * Vn + lane] = v;
    }
}

extern "C" void kernel_launch(void* const* d_in, const int* in_sizes, int n_in,
                              void* d_out, int out_size) {
    const int*   tokens  = (const int*)d_in[0];
    const int*   lengths = (const int*)d_in[1];
    const float* Wih0    = (const float*)d_in[2];
    const float* Whh0    = (const float*)d_in[3];
    const float* b0      = (const float*)d_in[4];
    const float* Wih_r   = (const float*)d_in[5];
    const float* Whh_r   = (const float*)d_in[6];
    const float* b_r     = (const float*)d_in[7];
    const float* Wout    = (const float*)d_in[8];
    const float* bout    = (const float*)d_in[9];
    float* out = (float*)d_out;

    static bool attrDone = false;
    if (!attrDone) {
        cudaFuncSetAttribute(rec_kernel<true>,
                             cudaFuncAttributeMaxDynamicSharedMemorySize, REC_SMEM);
        cudaFuncSetAttribute(rec_kernel<false>,
                             cudaFuncAttributeMaxDynamicSharedMemorySize, REC_SMEM);
        cudaFuncSetAttribute(gemmA,
                             cudaFuncAttributeMaxDynamicSharedMemorySize, GA_SMEM);
        attrDone = true;
    }

    dummy_kernel<<<1, 32>>>();   // keeps ncu -s 5 capture on rec_kernel<true>

    prep_kernel<<<1024, 256>>>(Wih0, Whh0, Wih_r, Whh_r, Wout);

    for (int l = 0; l < 3; l++) {
        zero_state<<<1024, 256>>>();
        if (l > 0) gemmA<<<dim3(32, 256), 256, GA_SMEM>>>(l);
        const float* bias = (l == 0) ? b0 : (b_r + (size_t)(l - 1) * Gn);
        if (l == 0)
            rec_kernel<true><<<128, 256, REC_SMEM>>>(l, bias, tokens, lengths, out);
        else
            rec_kernel<false><<<128, 256, REC_SMEM>>>(l, bias, tokens, lengths, out);
    }
    logits_kernel<<<1024, 256>>>(bout, lengths, out);
}